// round 6
// baseline (speedup 1.0000x reference)
#include <cuda_runtime.h>
#include <cuda_bf16.h>

// AGNNConv:
//   Xp = X @ W;  attn[e] = dot(Xp[row[e]], Xp[col[e]]) * w
//   out[i] = sum_{e: row[e]==i} attn[e] * Xp[col[e]]
// Inputs: X [N*64 f32], W [64*64 f32], attention_w [1 f32],
//         row [E i32 sorted], col [E i32].  Output: out [N*64 f32]

#define D 64
#define MAX_NODES 50000
#define EPG 16              // edges per 8-lane group
#define EPW (4 * EPG)       // edges per warp
#define RPB 128             // rows per block (gemm)
#define XS_STRIDE 76

__device__ float4 g_Xp4[MAX_NODES * (D / 4)];

// ---------------------------------------------------------------------------
// Kernel 1: Xp = X @ W + zero out.  256 threads, 128 rows/block.
// ---------------------------------------------------------------------------
__global__ void __launch_bounds__(256)
gemm_zero_kernel(const float4* __restrict__ X4, const float4* __restrict__ W4,
                 float4* __restrict__ out4, int n_nodes)
{
    __shared__ float Ws[D * D];
    __shared__ float Xs[RPB * XS_STRIDE];

    int t  = threadIdx.x;
    int r0 = blockIdx.x * RPB;

    float4* Ws4v = reinterpret_cast<float4*>(Ws);
    #pragma unroll
    for (int i = 0; i < 4; ++i) Ws4v[t + 256 * i] = W4[t + 256 * i];

    #pragma unroll
    for (int i = 0; i < 8; ++i) {
        int idx4 = t + 256 * i;
        int r  = idx4 >> 4;
        int k4 = idx4 & 15;
        float4 v = (r0 + r < n_nodes) ? X4[(r0 + r) * 16 + k4]
                                      : make_float4(0.f, 0.f, 0.f, 0.f);
        *reinterpret_cast<float4*>(&Xs[r * XS_STRIDE + k4 * 4]) = v;
    }
    __syncthreads();

    int rg = t >> 3;
    int dg = t & 7;

    float acc[4][8];
    #pragma unroll
    for (int i = 0; i < 4; ++i)
        #pragma unroll
        for (int j = 0; j < 8; ++j) acc[i][j] = 0.f;

    const float* xbase = &Xs[(rg * 4) * XS_STRIDE];
    const float4* Wq = reinterpret_cast<const float4*>(Ws) + dg * 2;

    #pragma unroll 4
    for (int k4 = 0; k4 < 16; ++k4) {
        float4 xv[4];
        #pragma unroll
        for (int i = 0; i < 4; ++i)
            xv[i] = *reinterpret_cast<const float4*>(
                        &xbase[i * XS_STRIDE + k4 * 4]);

        #pragma unroll
        for (int kk = 0; kk < 4; ++kk) {
            int k = k4 * 4 + kk;
            float4 w0 = Wq[k * 16];
            float4 w1 = Wq[k * 16 + 1];
            #pragma unroll
            for (int i = 0; i < 4; ++i) {
                float x = reinterpret_cast<const float*>(&xv[i])[kk];
                acc[i][0] = fmaf(x, w0.x, acc[i][0]);
                acc[i][1] = fmaf(x, w0.y, acc[i][1]);
                acc[i][2] = fmaf(x, w0.z, acc[i][2]);
                acc[i][3] = fmaf(x, w0.w, acc[i][3]);
                acc[i][4] = fmaf(x, w1.x, acc[i][4]);
                acc[i][5] = fmaf(x, w1.y, acc[i][5]);
                acc[i][6] = fmaf(x, w1.z, acc[i][6]);
                acc[i][7] = fmaf(x, w1.w, acc[i][7]);
            }
        }
    }

    float4 z = make_float4(0.f, 0.f, 0.f, 0.f);
    #pragma unroll
    for (int i = 0; i < 4; ++i) {
        int r = r0 + rg * 4 + i;
        if (r < n_nodes) {
            int base = r * 16 + dg * 2;
            g_Xp4[base]     = make_float4(acc[i][0], acc[i][1], acc[i][2], acc[i][3]);
            g_Xp4[base + 1] = make_float4(acc[i][4], acc[i][5], acc[i][6], acc[i][7]);
            out4[base]      = z;
            out4[base + 1]  = z;
        }
    }
}

// ---------------------------------------------------------------------------
// Kernel 2: edge SDDMM + register SpMM scatter.
// Warp = 4 groups of 8 lanes; group handles EPG contiguous edges; lane q owns
// quads q and q+8 (one 128B line per group load).
// Fast path (whole warp in range): NO per-edge predication, 1-deep prefetch of
// (row, col, xc) so L2 latency overlaps the 3-shfl reduce chain.
// Slow path (warp straddles the end): R4-style predicated loop, converged.
// ---------------------------------------------------------------------------
__global__ void __launch_bounds__(256, 5)
edge_kernel(const int* __restrict__ row, const int* __restrict__ col,
            const float* __restrict__ attn_w, float4* __restrict__ out4,
            int n_edges)
{
    int warp_id = (blockIdx.x * blockDim.x + threadIdx.x) >> 5;
    int lane    = threadIdx.x & 31;
    int q       = lane & 7;

    int wbase = warp_id * EPW;
    if (wbase >= n_edges) return;

    int e0 = wbase + (lane >> 3) * EPG;
    const float w = __ldg(attn_w);

    if (wbase + EPW <= n_edges) {
        // ---------------- fast path: no bounds checks ----------------
        int last = n_edges - 1;

        int r_cur = row[e0];
        float4 xc0 = g_Xp4[col[e0] * 16 + q];
        float4 xc1 = g_Xp4[col[e0] * 16 + 8 + q];

        int seg_r = r_cur;
        float4 xr0 = g_Xp4[seg_r * 16 + q];
        float4 xr1 = g_Xp4[seg_r * 16 + 8 + q];

        float4 acc0 = make_float4(0.f, 0.f, 0.f, 0.f);
        float4 acc1 = make_float4(0.f, 0.f, 0.f, 0.f);

        #pragma unroll
        for (int i = 0; i < EPG; ++i) {
            // prefetch edge i+1 (independent of this iteration's chain)
            int e_n = min(e0 + i + 1, last);
            int r_n = row[e_n];
            int c_n = col[e_n];
            float4 nxc0 = g_Xp4[c_n * 16 + q];
            float4 nxc1 = g_Xp4[c_n * 16 + 8 + q];

            if (r_cur != seg_r) {          // rare: avg 1 in 16
                atomicAdd(&out4[seg_r * 16 + q],     acc0);
                atomicAdd(&out4[seg_r * 16 + 8 + q], acc1);
                acc0 = make_float4(0.f, 0.f, 0.f, 0.f);
                acc1 = make_float4(0.f, 0.f, 0.f, 0.f);
                seg_r = r_cur;
                xr0 = g_Xp4[seg_r * 16 + q];
                xr1 = g_Xp4[seg_r * 16 + 8 + q];
            }

            float p = xc0.x * xr0.x + xc0.y * xr0.y + xc0.z * xr0.z + xc0.w * xr0.w
                    + xc1.x * xr1.x + xc1.y * xr1.y + xc1.z * xr1.z + xc1.w * xr1.w;
            p += __shfl_xor_sync(0xFFFFFFFFu, p, 4);
            p += __shfl_xor_sync(0xFFFFFFFFu, p, 2);
            p += __shfl_xor_sync(0xFFFFFFFFu, p, 1);

            float a = p * w;
            acc0.x = fmaf(a, xc0.x, acc0.x);
            acc0.y = fmaf(a, xc0.y, acc0.y);
            acc0.z = fmaf(a, xc0.z, acc0.z);
            acc0.w = fmaf(a, xc0.w, acc0.w);
            acc1.x = fmaf(a, xc1.x, acc1.x);
            acc1.y = fmaf(a, xc1.y, acc1.y);
            acc1.z = fmaf(a, xc1.z, acc1.z);
            acc1.w = fmaf(a, xc1.w, acc1.w);

            r_cur = r_n; xc0 = nxc0; xc1 = nxc1;
        }

        atomicAdd(&out4[seg_r * 16 + q],     acc0);
        atomicAdd(&out4[seg_r * 16 + 8 + q], acc1);
    } else {
        // ---------------- slow path: predicated, warp stays converged ------
        bool any  = e0 < n_edges;
        int e_end = any ? min(e0 + EPG, n_edges) : 0;
        int e_safe = any ? e0 : 0;

        int cur_r = row[e_safe];
        float4 xr0 = g_Xp4[cur_r * 16 + q];
        float4 xr1 = g_Xp4[cur_r * 16 + 8 + q];
        float4 acc0 = make_float4(0.f, 0.f, 0.f, 0.f);
        float4 acc1 = make_float4(0.f, 0.f, 0.f, 0.f);

        for (int i = 0; i < EPG; ++i) {
            int e = e0 + i;
            bool valid = any && (e < e_end);
            int ec = valid ? e : e_safe;

            int r = row[ec];
            int c = col[ec];

            if (valid && r != cur_r) {
                atomicAdd(&out4[cur_r * 16 + q],     acc0);
                atomicAdd(&out4[cur_r * 16 + 8 + q], acc1);
                acc0 = make_float4(0.f, 0.f, 0.f, 0.f);
                acc1 = make_float4(0.f, 0.f, 0.f, 0.f);
                cur_r = r;
                xr0 = g_Xp4[r * 16 + q];
                xr1 = g_Xp4[r * 16 + 8 + q];
            }

            float4 xc0 = g_Xp4[c * 16 + q];
            float4 xc1 = g_Xp4[c * 16 + 8 + q];
            float p = xc0.x * xr0.x + xc0.y * xr0.y + xc0.z * xr0.z + xc0.w * xr0.w
                    + xc1.x * xr1.x + xc1.y * xr1.y + xc1.z * xr1.z + xc1.w * xr1.w;
            p += __shfl_xor_sync(0xFFFFFFFFu, p, 4);
            p += __shfl_xor_sync(0xFFFFFFFFu, p, 2);
            p += __shfl_xor_sync(0xFFFFFFFFu, p, 1);

            if (valid) {
                float a = p * w;
                acc0.x = fmaf(a, xc0.x, acc0.x);
                acc0.y = fmaf(a, xc0.y, acc0.y);
                acc0.z = fmaf(a, xc0.z, acc0.z);
                acc0.w = fmaf(a, xc0.w, acc0.w);
                acc1.x = fmaf(a, xc1.x, acc1.x);
                acc1.y = fmaf(a, xc1.y, acc1.y);
                acc1.z = fmaf(a, xc1.z, acc1.z);
                acc1.w = fmaf(a, xc1.w, acc1.w);
            }
        }

        if (any) {
            atomicAdd(&out4[cur_r * 16 + q],     acc0);
            atomicAdd(&out4[cur_r * 16 + 8 + q], acc1);
        }
    }
}

// ---------------------------------------------------------------------------
extern "C" void kernel_launch(void* const* d_in, const int* in_sizes, int n_in,
                              void* d_out, int out_size)
{
    const float4* X4 = (const float4*)d_in[0];
    const float4* W4 = (const float4*)d_in[1];
    const float*  aw = (const float*)d_in[2];
    const int*   row = (const int*)d_in[3];
    const int*   col = (const int*)d_in[4];
    float4* out4 = (float4*)d_out;

    int n_nodes = in_sizes[0] / D;
    int n_edges = in_sizes[3];

    gemm_zero_kernel<<<(n_nodes + RPB - 1) / RPB, 256>>>(X4, W4, out4, n_nodes);

    int n_warps  = (n_edges + EPW - 1) / EPW;
    int n_blocks = (n_warps + 7) / 8;
    edge_kernel<<<n_blocks, 256>>>(row, col, aw, out4, n_edges);
}